// round 2
// baseline (speedup 1.0000x reference)
#include <cuda_runtime.h>
#include <math.h>
#include <float.h>

#define NN 50000
#define EE 800000
#define FF 128
#define HH 64
#define HEADS 4
#define LL 3
#define GG 64
#define NCLS 2
#define EPS 1e-5f

// ---------------- scratch (device globals; no allocation allowed) ----------
__device__ float g_h[NN * HH];          // current node features
__device__ float g_hw[NN * HH];         // h @ W (per GCN layer)
__device__ float g_acc[NN * HH];        // scatter accumulator
__device__ float g_hg[NN * HEADS * HH]; // GAT transformed features
__device__ float g_dinv[NN];
__device__ float g_deg[NN];
__device__ float g_as[NN * HEADS];
__device__ float g_ad[NN * HEADS];
__device__ float g_m[NN * HEADS];
__device__ float g_s[NN * HEADS];
__device__ float g_alpha[EE * HEADS];
__device__ double g_bnsum[HH];
__device__ double g_bnsq[HH];
__device__ float g_psum[GG * HH];
__device__ float g_pmax[GG * HH];
__device__ float g_pcnt[GG];

// ---------------- helpers ---------------------------------------------------
__device__ __forceinline__ void atomicMaxF(float* addr, float v) {
    if (v >= 0.f)
        atomicMax((int*)addr, __float_as_int(v));
    else
        atomicMin((unsigned int*)addr, __float_as_uint(v));
}

__device__ __forceinline__ float lrelu02(float x) {
    return x > 0.f ? x : 0.2f * x;
}

// ---------------- generic row-GEMM: Y[n, 0..M) = X[n, 0..K) @ W[K, M] ------
// IN:  0 -> use param X      1 -> g_h
// OUT: 0 -> g_h   1 -> g_hw   2 -> g_hg
template <int K, int M, int NB, bool BIAS_RELU, int IN, int OUT>
__global__ void node_gemm(const float* __restrict__ Xp, const float* __restrict__ W,
                          const float* __restrict__ bias) {
    const float* __restrict__ X = (IN == 0) ? Xp : (const float*)g_h;
    float* __restrict__ Y = (OUT == 0) ? g_h : (OUT == 1) ? g_hw : g_hg;
    __shared__ float xs[NB][K];
    const int j = threadIdx.x;   // output column
    const int yn = threadIdx.y;  // node within block
    const int base = blockIdx.x * NB;
    const int tid = yn * M + j;
    for (int i = tid; i < NB * K; i += M * NB) {
        int nn = i / K, kk = i - nn * K;
        int node = base + nn;
        xs[nn][kk] = (node < NN) ? X[node * K + kk] : 0.f;
    }
    __syncthreads();
    const int node = base + yn;
    if (node >= NN) return;
    float acc = 0.f;
#pragma unroll
    for (int k = 0; k < K; ++k) acc += xs[yn][k] * W[k * M + j];
    if (BIAS_RELU) acc = fmaxf(acc + bias[j], 0.f);
    Y[node * M + j] = acc;
}

// ---------------- degree / dinv ---------------------------------------------
__global__ void zero_deg() {
    int i = blockIdx.x * blockDim.x + threadIdx.x;
    if (i < NN) g_deg[i] = 0.f;
}
__global__ void deg_edges(const int* __restrict__ ei) {
    int e = blockIdx.x * blockDim.x + threadIdx.x;
    if (e < EE) atomicAdd(&g_deg[ei[EE + e]], 1.f);
}
__global__ void make_dinv() {
    int i = blockIdx.x * blockDim.x + threadIdx.x;
    if (i < NN) g_dinv[i] = rsqrtf(g_deg[i] + 1.f);
}

// ---------------- GCN -------------------------------------------------------
__global__ void gcn_init() {
    int idx = blockIdx.x * blockDim.x + threadIdx.x;
    if (idx >= NN * HH) return;
    int n = idx >> 6;
    float d = g_dinv[n];
    g_acc[idx] = g_hw[idx] * d * d;
}
__global__ void gcn_scatter(const int* __restrict__ ei) {
    long long idx = (long long)blockIdx.x * blockDim.x + threadIdx.x;
    if (idx >= (long long)EE * HH) return;
    int e = (int)(idx >> 6);
    int c = (int)(idx & 63);
    int src = ei[e];
    int dst = ei[EE + e];
    float v = g_hw[src * HH + c] * g_dinv[src] * g_dinv[dst];
    atomicAdd(&g_acc[dst * HH + c], v);
}

// ---------------- BN stats / apply ------------------------------------------
__global__ void zero_bn() {
    int t = threadIdx.x;
    if (t < HH) { g_bnsum[t] = 0.0; g_bnsq[t] = 0.0; }
}
__global__ void bn_stats() {
    __shared__ double ss[8][HH];
    __shared__ double sq[8][HH];
    int c = threadIdx.x, ty = threadIdx.y;
    double s = 0.0, q = 0.0;
    for (int r = blockIdx.x * 8 + ty; r < NN; r += gridDim.x * 8) {
        double v = (double)g_acc[r * HH + c];
        s += v; q += v * v;
    }
    ss[ty][c] = s; sq[ty][c] = q;
    __syncthreads();
    if (ty == 0) {
#pragma unroll
        for (int t = 1; t < 8; ++t) { s += ss[t][c]; q += sq[t][c]; }
        atomicAdd(&g_bnsum[c], s);
        atomicAdd(&g_bnsq[c], q);
    }
}
template <bool ELU>
__global__ void bn_apply_residual(const float* __restrict__ gamma,
                                  const float* __restrict__ beta) {
    int idx = blockIdx.x * blockDim.x + threadIdx.x;
    if (idx >= NN * HH) return;
    int c = idx & 63;
    double mu = g_bnsum[c] / (double)NN;
    double var = g_bnsq[c] / (double)NN - mu * mu;
    float v = (g_acc[idx] - (float)mu) * rsqrtf((float)var + EPS) * gamma[c] + beta[c];
    float act;
    if (ELU) act = v > 0.f ? v : (expf(v) - 1.f);
    else     act = fmaxf(v, 0.f);
    g_h[idx] = act + g_h[idx];
}

// ---------------- GAT -------------------------------------------------------
__global__ void gat_dots(const float* __restrict__ att_s, const float* __restrict__ att_d) {
    int gt = blockIdx.x * blockDim.x + threadIdx.x;
    int gw = gt >> 5;
    int lane = gt & 31;
    if (gw >= NN * HEADS) return;
    int n = gw >> 2, hd = gw & 3;
    const float* row = g_hg + n * (HEADS * HH) + hd * HH;
    float v0 = row[lane], v1 = row[lane + 32];
    float s1 = v0 * att_s[hd * HH + lane] + v1 * att_s[hd * HH + lane + 32];
    float s2 = v0 * att_d[hd * HH + lane] + v1 * att_d[hd * HH + lane + 32];
#pragma unroll
    for (int o = 16; o; o >>= 1) {
        s1 += __shfl_down_sync(0xffffffffu, s1, o);
        s2 += __shfl_down_sync(0xffffffffu, s2, o);
    }
    if (lane == 0) {
        g_as[gw] = s1;
        g_ad[gw] = s2;
        g_m[gw] = lrelu02(s1 + s2);  // self-loop logit as init for segment max
    }
}
__global__ void gat_edge_max(const int* __restrict__ ei) {
    int idx = blockIdx.x * blockDim.x + threadIdx.x;
    if (idx >= EE * HEADS) return;
    int e = idx >> 2, hd = idx & 3;
    int src = ei[e], dst = ei[EE + e];
    float lg = lrelu02(g_as[src * HEADS + hd] + g_ad[dst * HEADS + hd]);
    atomicMaxF(&g_m[dst * HEADS + hd], lg);
}
__global__ void gat_self_exp() {
    int idx = blockIdx.x * blockDim.x + threadIdx.x;
    if (idx >= NN * HEADS) return;
    float lg = lrelu02(g_as[idx] + g_ad[idx]);
    g_s[idx] = expf(lg - g_m[idx]);
}
__global__ void gat_edge_exp(const int* __restrict__ ei) {
    int idx = blockIdx.x * blockDim.x + threadIdx.x;
    if (idx >= EE * HEADS) return;
    int e = idx >> 2, hd = idx & 3;
    int src = ei[e], dst = ei[EE + e];
    float lg = lrelu02(g_as[src * HEADS + hd] + g_ad[dst * HEADS + hd]);
    float t = expf(lg - g_m[dst * HEADS + hd]);
    g_alpha[idx] = t;
    atomicAdd(&g_s[dst * HEADS + hd], t);
}
__global__ void gat_alpha_div(const int* __restrict__ ei) {
    int idx = blockIdx.x * blockDim.x + threadIdx.x;
    if (idx >= EE * HEADS) return;
    int e = idx >> 2, hd = idx & 3;
    int dst = ei[EE + e];
    g_alpha[idx] = g_alpha[idx] / (g_s[dst * HEADS + hd] + 1e-16f);
}
__global__ void gat_init_acc() {
    int idx = blockIdx.x * blockDim.x + threadIdx.x;
    if (idx >= NN * HH) return;
    int n = idx >> 6, c = idx & 63;
    float acc = 0.f;
#pragma unroll
    for (int hd = 0; hd < HEADS; ++hd) {
        int w = n * HEADS + hd;
        float lg = lrelu02(g_as[w] + g_ad[w]);
        float a = expf(lg - g_m[w]) / (g_s[w] + 1e-16f);
        acc += a * g_hg[n * (HEADS * HH) + hd * HH + c];
    }
    g_acc[idx] = 0.25f * acc;
}
__global__ void gat_edge_scatter(const int* __restrict__ ei) {
    long long idx = (long long)blockIdx.x * blockDim.x + threadIdx.x;
    if (idx >= (long long)EE * HH) return;
    int e = (int)(idx >> 6);
    int c = (int)(idx & 63);
    int src = ei[e], dst = ei[EE + e];
    float v = 0.f;
#pragma unroll
    for (int hd = 0; hd < HEADS; ++hd)
        v += g_alpha[e * HEADS + hd] * g_hg[src * (HEADS * HH) + hd * HH + c];
    atomicAdd(&g_acc[dst * HH + c], 0.25f * v);
}

// ---------------- pooling + MLP ---------------------------------------------
__global__ void pool_init() {
    int idx = blockIdx.x * blockDim.x + threadIdx.x;
    if (idx < GG * HH) { g_psum[idx] = 0.f; g_pmax[idx] = -FLT_MAX; }
    if (idx < GG) g_pcnt[idx] = 0.f;
}
__global__ void pool_scatter(const int* __restrict__ batch) {
    int idx = blockIdx.x * blockDim.x + threadIdx.x;
    if (idx >= NN * HH) return;
    int n = idx >> 6, c = idx & 63;
    int g = batch[n];
    float v = g_h[idx];
    atomicAdd(&g_psum[g * HH + c], v);
    atomicMaxF(&g_pmax[g * HH + c], v);
    if (c == 0) atomicAdd(&g_pcnt[g], 1.f);
}
__global__ void mlp_kernel(const float* __restrict__ c1W, const float* __restrict__ c1b,
                           const float* __restrict__ c2W, const float* __restrict__ c2b,
                           const float* __restrict__ c3W, const float* __restrict__ c3b,
                           float* __restrict__ out) {
    __shared__ float z[2 * HH];
    __shared__ float z1[HH];
    __shared__ float z2[HH / 2];
    int g = blockIdx.x, t = threadIdx.x;
    if (t < HH) {
        float cnt = g_pcnt[g];
        float mean = g_psum[g * HH + t] / fmaxf(cnt, 1.f);
        float mx = g_pmax[g * HH + t];
        if (cnt < 0.5f) mx = 0.f;  // segment_max over empty segment -> -inf -> 0
        z[t] = mean;
        z[HH + t] = mx;
    }
    __syncthreads();
    if (t < HH) {
        float a = c1b[t];
#pragma unroll 4
        for (int k = 0; k < 2 * HH; ++k) a += z[k] * c1W[k * HH + t];
        z1[t] = fmaxf(a, 0.f);
    }
    __syncthreads();
    if (t < HH / 2) {
        float a = c2b[t];
#pragma unroll 4
        for (int k = 0; k < HH; ++k) a += z1[k] * c2W[k * (HH / 2) + t];
        z2[t] = fmaxf(a, 0.f);
    }
    __syncthreads();
    if (t < NCLS) {
        float a = c3b[t];
#pragma unroll
        for (int k = 0; k < HH / 2; ++k) a += z2[k] * c3W[k * NCLS + t];
        out[g * NCLS + t] = a;
    }
}

// ---------------- launch ----------------------------------------------------
extern "C" void kernel_launch(void* const* d_in, const int* in_sizes, int n_in,
                              void* d_out, int out_size) {
    const float* x       = (const float*)d_in[0];
    const int*   ei      = (const int*)d_in[1];
    const int*   batch   = (const int*)d_in[2];
    const float* Wi      = (const float*)d_in[3];
    const float* bi      = (const float*)d_in[4];
    const float* gcn_W   = (const float*)d_in[5];
    // d_in[6] gcn_b: cancels under training-mode BN (constant per-channel shift)
    const float* gcn_gamma = (const float*)d_in[7];
    const float* gcn_beta  = (const float*)d_in[8];
    const float* Wg      = (const float*)d_in[9];
    // d_in[10] bg: cancels under BN
    const float* att_src = (const float*)d_in[11];
    const float* att_dst = (const float*)d_in[12];
    const float* gat_gamma = (const float*)d_in[13];
    const float* gat_beta  = (const float*)d_in[14];
    const float* c1_W = (const float*)d_in[15];
    const float* c1_b = (const float*)d_in[16];
    const float* c2_W = (const float*)d_in[17];
    const float* c2_b = (const float*)d_in[18];
    const float* c3_W = (const float*)d_in[19];
    const float* c3_b = (const float*)d_in[20];
    float* out = (float*)d_out;

    const int NH = NN * HH;                       // 3.2M
    const int nh_blocks = (NH + 255) / 256;       // 12500
    const long long EH = (long long)EE * HH;      // 51.2M
    const int eh_blocks = (int)((EH + 255) / 256);
    const int e4_blocks = (EE * HEADS + 255) / 256;
    const int n4_blocks = (NN * HEADS + 255) / 256;

    // 1. input linear + relu  (x -> g_h)
    node_gemm<FF, HH, 4, true, 0, 0><<<(NN + 3) / 4, dim3(HH, 4)>>>(x, Wi, bi);

    // 2. degrees (dst-based, shared by all GCN layers)
    zero_deg<<<(NN + 255) / 256, 256>>>();
    deg_edges<<<(EE + 255) / 256, 256>>>(ei);
    make_dinv<<<(NN + 255) / 256, 256>>>();

    // 3. GCN layers
    for (int l = 0; l < LL; ++l) {
        node_gemm<HH, HH, 4, false, 1, 1><<<(NN + 3) / 4, dim3(HH, 4)>>>(
            nullptr, gcn_W + l * HH * HH, nullptr);
        gcn_init<<<nh_blocks, 256>>>();
        gcn_scatter<<<eh_blocks, 256>>>(ei);
        zero_bn<<<1, HH>>>();
        bn_stats<<<128, dim3(HH, 8)>>>();
        bn_apply_residual<false><<<nh_blocks, 256>>>(gcn_gamma + l * HH, gcn_beta + l * HH);
    }

    // 4. GAT  (g_h -> g_hg)
    node_gemm<HH, HEADS * HH, 1, false, 1, 2><<<NN, dim3(HEADS * HH, 1)>>>(nullptr, Wg, nullptr);
    gat_dots<<<(NN * HEADS * 32 + 255) / 256, 256>>>(att_src, att_dst);
    gat_edge_max<<<e4_blocks, 256>>>(ei);
    gat_self_exp<<<n4_blocks, 256>>>();
    gat_edge_exp<<<e4_blocks, 256>>>(ei);
    gat_alpha_div<<<e4_blocks, 256>>>(ei);
    gat_init_acc<<<nh_blocks, 256>>>();
    gat_edge_scatter<<<eh_blocks, 256>>>(ei);
    zero_bn<<<1, HH>>>();
    bn_stats<<<128, dim3(HH, 8)>>>();
    bn_apply_residual<true><<<nh_blocks, 256>>>(gat_gamma, gat_beta);

    // 5. pooling + MLP
    pool_init<<<(GG * HH + 255) / 256, 256>>>();
    pool_scatter<<<nh_blocks, 256>>>(batch);
    mlp_kernel<<<GG, 128>>>(c1_W, c1_b, c2_W, c2_b, c3_W, c3_b, out);
}

// round 3
// speedup vs baseline: 2.2561x; 2.2561x over previous
#include <cuda_runtime.h>
#include <math.h>
#include <float.h>

#define NN 50000
#define EE 800000
#define FF 128
#define HH 64
#define HEADS 4
#define LL 3
#define GG 64
#define NCLS 2
#define EPS 1e-5f

// ---------------- scratch (device globals) ----------------------------------
__device__ float g_h[NN * HH];
__device__ float g_hw[NN * HH];
__device__ float g_acc[NN * HH];
__device__ float g_hg[NN * HEADS * HH];
__device__ float g_dinv[NN];
__device__ int   g_degi[NN];
__device__ int   g_off[NN];
__device__ int   g_cur[NN];
__device__ int   g_srcs[EE];   // src node per dst-sorted position
__device__ int   g_dsts[EE];   // dst node per dst-sorted position
__device__ float g_as[NN * HEADS];
__device__ float g_ad[NN * HEADS];
__device__ float g_m[NN * HEADS];
__device__ float g_s[NN * HEADS];
__device__ float g_aself[NN * HEADS];
__device__ float g_alpha[EE * HEADS];
__device__ double g_bnsum[HH];
__device__ double g_bnsq[HH];
__device__ float g_bnmu[HH];
__device__ float g_bnrstd[HH];
__device__ float g_psum[GG * HH];
__device__ float g_pmax[GG * HH];
__device__ float g_pcnt[GG];

// ---------------- helpers ----------------------------------------------------
__device__ __forceinline__ void atomicMaxF(float* addr, float v) {
    if (v >= 0.f) atomicMax((int*)addr, __float_as_int(v));
    else          atomicMin((unsigned int*)addr, __float_as_uint(v));
}
__device__ __forceinline__ float lrelu02(float x) { return x > 0.f ? x : 0.2f * x; }

// ---------------- tiled GEMM: Y[n,0..M) = X[n,0..K) @ W[K,M] -----------------
// IN: 0 -> param X, 1 -> g_h ;  OUT: 0 -> g_h, 1 -> g_hw, 2 -> g_hg
template <int K, int M, bool BIAS_RELU, int IN, int OUT>
__global__ void gemm64(const float* __restrict__ Xp, const float* __restrict__ W,
                       const float* __restrict__ bias) {
    const float* __restrict__ X = (IN == 0) ? Xp : (const float*)g_h;
    float* __restrict__ Y = (OUT == 0) ? g_h : (OUT == 1) ? g_hw : g_hg;
    __shared__ float xs[64][65];
    __shared__ float ws[64][65];
    const int tid = threadIdx.x;
    const int tx = tid & 15, ty = tid >> 4;
    const int nb = blockIdx.x * 64;
    const int mb = blockIdx.y * 64;
    float acc[4][4];
#pragma unroll
    for (int i = 0; i < 4; ++i)
#pragma unroll
        for (int j = 0; j < 4; ++j) acc[i][j] = 0.f;

    for (int kc = 0; kc < K; kc += 64) {
        // stage X tile [64 nodes][64 k]
#pragma unroll
        for (int u = 0; u < 16; ++u) {
            int i = tid + u * 256;
            int node = i >> 6, k = i & 63;
            int gn = nb + node;
            xs[node][k] = (gn < NN) ? X[gn * K + kc + k] : 0.f;
        }
        // stage W tile [64 k][64 m]
#pragma unroll
        for (int u = 0; u < 16; ++u) {
            int i = tid + u * 256;
            int k = i >> 6, m = i & 63;
            ws[k][m] = W[(kc + k) * M + mb + m];
        }
        __syncthreads();
#pragma unroll
        for (int k = 0; k < 64; ++k) {
            float xv[4], wv[4];
#pragma unroll
            for (int i = 0; i < 4; ++i) xv[i] = xs[ty + 16 * i][k];
#pragma unroll
            for (int j = 0; j < 4; ++j) wv[j] = ws[k][tx + 16 * j];
#pragma unroll
            for (int i = 0; i < 4; ++i)
#pragma unroll
                for (int j = 0; j < 4; ++j) acc[i][j] += xv[i] * wv[j];
        }
        __syncthreads();
    }
#pragma unroll
    for (int i = 0; i < 4; ++i) {
        int gn = nb + ty + 16 * i;
        if (gn >= NN) continue;
#pragma unroll
        for (int j = 0; j < 4; ++j) {
            int col = tx + 16 * j;
            float v = acc[i][j];
            if (BIAS_RELU) v = fmaxf(v + bias[mb + col], 0.f);
            Y[gn * M + mb + col] = v;
        }
    }
}

// ---------------- CSR build ---------------------------------------------------
__global__ void zero_degi() {
    int i = blockIdx.x * blockDim.x + threadIdx.x;
    if (i < NN) g_degi[i] = 0;
}
__global__ void hist_dst(const int* __restrict__ ei) {
    int e = blockIdx.x * blockDim.x + threadIdx.x;
    if (e < EE) atomicAdd(&g_degi[ei[EE + e]], 1);
}
__global__ void scan_offsets() {  // 1 block, 1024 threads
    const int CH = (NN + 1023) / 1024;  // 49
    __shared__ int wsum[32];
    int t = threadIdx.x;
    int i0 = t * CH;
    int i1 = min(i0 + CH, NN);
    int s = 0;
    for (int i = i0; i < i1; ++i) s += g_degi[i];
    int lane = t & 31, wid = t >> 5;
    int v = s;
#pragma unroll
    for (int o = 1; o < 32; o <<= 1) {
        int u = __shfl_up_sync(0xffffffffu, v, o);
        if (lane >= o) v += u;
    }
    if (lane == 31) wsum[wid] = v;
    __syncthreads();
    if (wid == 0) {
        int w = wsum[lane];
#pragma unroll
        for (int o = 1; o < 32; o <<= 1) {
            int u = __shfl_up_sync(0xffffffffu, w, o);
            if (lane >= o) w += u;
        }
        wsum[lane] = w;
    }
    __syncthreads();
    int run = (wid ? wsum[wid - 1] : 0) + v - s;
    for (int i = i0; i < i1; ++i) {
        g_off[i] = run;
        g_cur[i] = run;
        g_dinv[i] = rsqrtf((float)g_degi[i] + 1.f);
        run += g_degi[i];
    }
}
__global__ void fill_csr(const int* __restrict__ ei) {
    int e = blockIdx.x * blockDim.x + threadIdx.x;
    if (e >= EE) return;
    int src = ei[e], dst = ei[EE + e];
    int pos = atomicAdd(&g_cur[dst], 1);
    g_srcs[pos] = src;
    g_dsts[pos] = dst;
}

// ---------------- GCN gather --------------------------------------------------
__global__ void gcn_gather() {  // 256 thr = 4 nodes x 64 ch
    int t = threadIdx.x;
    int c = t & 63;
    int n = blockIdx.x * 4 + (t >> 6);
    if (n >= NN) return;
    float dn = g_dinv[n];
    int start = g_off[n], deg = g_degi[n];
    float acc = g_hw[n * HH + c] * dn * dn;
    int k = 0;
    for (; k + 2 <= deg; k += 2) {
        int s0 = g_srcs[start + k];
        int s1 = g_srcs[start + k + 1];
        float d0 = g_dinv[s0], d1 = g_dinv[s1];
        float v0 = g_hw[s0 * HH + c];
        float v1 = g_hw[s1 * HH + c];
        acc += v0 * d0 * dn + v1 * d1 * dn;
    }
    if (k < deg) {
        int s0 = g_srcs[start + k];
        acc += g_hw[s0 * HH + c] * g_dinv[s0] * dn;
    }
    g_acc[n * HH + c] = acc;
}

// ---------------- BN ----------------------------------------------------------
__global__ void zero_bn() {
    int t = threadIdx.x;
    if (t < HH) { g_bnsum[t] = 0.0; g_bnsq[t] = 0.0; }
}
__global__ void bn_stats() {
    __shared__ double ss[8][HH];
    __shared__ double sq[8][HH];
    int c = threadIdx.x, ty = threadIdx.y;
    double s = 0.0, q = 0.0;
    for (int r = blockIdx.x * 8 + ty; r < NN; r += gridDim.x * 8) {
        double v = (double)g_acc[r * HH + c];
        s += v; q += v * v;
    }
    ss[ty][c] = s; sq[ty][c] = q;
    __syncthreads();
    if (ty == 0) {
#pragma unroll
        for (int t = 1; t < 8; ++t) { s += ss[t][c]; q += sq[t][c]; }
        atomicAdd(&g_bnsum[c], s);
        atomicAdd(&g_bnsq[c], q);
    }
}
__global__ void bn_finalize(const float* __restrict__ gamma, const float* __restrict__ beta) {
    int c = threadIdx.x;
    if (c >= HH) return;
    double mu = g_bnsum[c] / (double)NN;
    double var = g_bnsq[c] / (double)NN - mu * mu;
    g_bnmu[c] = (float)mu;
    g_bnrstd[c] = rsqrtf((float)var + EPS) * gamma[c];
    // store beta in mu slot trick avoided; beta applied in apply kernel via param
    (void)beta;
}
template <bool ELU>
__global__ void bn_apply_residual(const float* __restrict__ beta) {
    int idx = blockIdx.x * blockDim.x + threadIdx.x;
    if (idx >= NN * HH) return;
    int c = idx & 63;
    float v = (g_acc[idx] - g_bnmu[c]) * g_bnrstd[c] + beta[c];
    float act;
    if (ELU) act = v > 0.f ? v : (expf(v) - 1.f);
    else     act = fmaxf(v, 0.f);
    g_h[idx] = act + g_h[idx];
}

// ---------------- GAT ----------------------------------------------------------
__global__ void gat_dots(const float* __restrict__ att_s, const float* __restrict__ att_d) {
    int gt = blockIdx.x * blockDim.x + threadIdx.x;
    int gw = gt >> 5;
    int lane = gt & 31;
    if (gw >= NN * HEADS) return;
    int n = gw >> 2, hd = gw & 3;
    const float* row = g_hg + n * (HEADS * HH) + hd * HH;
    float v0 = row[lane], v1 = row[lane + 32];
    float s1 = v0 * att_s[hd * HH + lane] + v1 * att_s[hd * HH + lane + 32];
    float s2 = v0 * att_d[hd * HH + lane] + v1 * att_d[hd * HH + lane + 32];
#pragma unroll
    for (int o = 16; o; o >>= 1) {
        s1 += __shfl_down_sync(0xffffffffu, s1, o);
        s2 += __shfl_down_sync(0xffffffffu, s2, o);
    }
    if (lane == 0) { g_as[gw] = s1; g_ad[gw] = s2; }
}
// per-node online (max, sum-exp) per head; warp per node
__global__ void gat_ms() {
    int warp = (blockIdx.x * blockDim.x + threadIdx.x) >> 5;
    int lane = threadIdx.x & 31;
    if (warp >= NN) return;
    int n = warp;
    int hd = lane & 3, k0 = lane >> 2;  // 8 edge lanes per head
    float adv = g_ad[n * HEADS + hd];
    float asv = g_as[n * HEADS + hd];
    float lg_self = lrelu02(asv + adv);
    float m = -FLT_MAX, s = 0.f;
    if (k0 == 0) { m = lg_self; s = 1.f; }  // self loop
    int start = g_off[n], deg = g_degi[n];
    for (int k = k0; k < deg; k += 8) {
        int sr = g_srcs[start + k];
        float lg = lrelu02(g_as[sr * HEADS + hd] + adv);
        if (lg > m) { s = s * expf(m - lg) + 1.f; m = lg; }
        else        { s += expf(lg - m); }
    }
#pragma unroll
    for (int o = 4; o < 32; o <<= 1) {
        float mo = __shfl_xor_sync(0xffffffffu, m, o);
        float so = __shfl_xor_sync(0xffffffffu, s, o);
        float M = fmaxf(m, mo);
        s = s * expf(m - M) + so * expf(mo - M);
        m = M;
    }
    if (lane < 4) {
        g_m[n * HEADS + hd] = m;
        g_s[n * HEADS + hd] = s;
        g_aself[n * HEADS + hd] = expf(lg_self - m) / (s + 1e-16f);
    }
}
__global__ void gat_alpha() {
    int idx = blockIdx.x * blockDim.x + threadIdx.x;
    if (idx >= EE * HEADS) return;
    int pos = idx >> 2, hd = idx & 3;
    int sr = g_srcs[pos], d = g_dsts[pos];
    float lg = lrelu02(g_as[sr * HEADS + hd] + g_ad[d * HEADS + hd]);
    g_alpha[idx] = expf(lg - g_m[d * HEADS + hd]) / (g_s[d * HEADS + hd] + 1e-16f);
}
__global__ void gat_gather() {  // 256 thr = 4 nodes x 64 ch
    int t = threadIdx.x;
    int c = t & 63;
    int n = blockIdx.x * 4 + (t >> 6);
    if (n >= NN) return;
    const float* hgn = g_hg + n * (HEADS * HH);
    float acc = g_aself[n * HEADS + 0] * hgn[c]
              + g_aself[n * HEADS + 1] * hgn[HH + c]
              + g_aself[n * HEADS + 2] * hgn[2 * HH + c]
              + g_aself[n * HEADS + 3] * hgn[3 * HH + c];
    int start = g_off[n], deg = g_degi[n];
    for (int k = 0; k < deg; ++k) {
        int sr = g_srcs[start + k];
        float4 al = *(const float4*)&g_alpha[(start + k) * 4];
        const float* hgs = g_hg + sr * (HEADS * HH);
        acc += al.x * hgs[c] + al.y * hgs[HH + c] + al.z * hgs[2 * HH + c] + al.w * hgs[3 * HH + c];
    }
    g_acc[n * HH + c] = 0.25f * acc;
}

// ---------------- pooling + MLP -------------------------------------------------
__global__ void pool_init() {
    int idx = blockIdx.x * blockDim.x + threadIdx.x;
    if (idx < GG * HH) { g_psum[idx] = 0.f; g_pmax[idx] = -FLT_MAX; }
    if (idx < GG) g_pcnt[idx] = 0.f;
}
__global__ void pool_reduce(const int* __restrict__ batch) {  // 64 thr, 128 nodes/block
    int c = threadIdx.x;
    int n0 = blockIdx.x * 128;
    int n1 = min(n0 + 128, NN);
    if (n0 >= NN) return;
    int cur = batch[n0];
    float sum = 0.f, mx = -FLT_MAX;
    int cnt = 0;
    for (int n = n0; n < n1; ++n) {
        int b = batch[n];
        if (b != cur) {
            atomicAdd(&g_psum[cur * HH + c], sum);
            atomicMaxF(&g_pmax[cur * HH + c], mx);
            if (c == 0) atomicAdd(&g_pcnt[cur], (float)cnt);
            sum = 0.f; mx = -FLT_MAX; cnt = 0; cur = b;
        }
        float v = g_h[n * HH + c];
        sum += v;
        mx = fmaxf(mx, v);
        cnt++;
    }
    atomicAdd(&g_psum[cur * HH + c], sum);
    atomicMaxF(&g_pmax[cur * HH + c], mx);
    if (c == 0) atomicAdd(&g_pcnt[cur], (float)cnt);
}
__global__ void mlp_kernel(const float* __restrict__ c1W, const float* __restrict__ c1b,
                           const float* __restrict__ c2W, const float* __restrict__ c2b,
                           const float* __restrict__ c3W, const float* __restrict__ c3b,
                           float* __restrict__ out) {
    __shared__ float z[2 * HH];
    __shared__ float z1[HH];
    __shared__ float z2[HH / 2];
    int g = blockIdx.x, t = threadIdx.x;
    if (t < HH) {
        float cnt = g_pcnt[g];
        float mean = g_psum[g * HH + t] / fmaxf(cnt, 1.f);
        float mx = g_pmax[g * HH + t];
        if (cnt < 0.5f) mx = 0.f;
        z[t] = mean;
        z[HH + t] = mx;
    }
    __syncthreads();
    if (t < HH) {
        float a = c1b[t];
#pragma unroll 4
        for (int k = 0; k < 2 * HH; ++k) a += z[k] * c1W[k * HH + t];
        z1[t] = fmaxf(a, 0.f);
    }
    __syncthreads();
    if (t < HH / 2) {
        float a = c2b[t];
#pragma unroll 4
        for (int k = 0; k < HH; ++k) a += z1[k] * c2W[k * (HH / 2) + t];
        z2[t] = fmaxf(a, 0.f);
    }
    __syncthreads();
    if (t < NCLS) {
        float a = c3b[t];
#pragma unroll
        for (int k = 0; k < HH / 2; ++k) a += z2[k] * c3W[k * NCLS + t];
        out[g * NCLS + t] = a;
    }
}

// ---------------- launch ----------------------------------------------------
extern "C" void kernel_launch(void* const* d_in, const int* in_sizes, int n_in,
                              void* d_out, int out_size) {
    const float* x       = (const float*)d_in[0];
    const int*   ei      = (const int*)d_in[1];
    const int*   batch   = (const int*)d_in[2];
    const float* Wi      = (const float*)d_in[3];
    const float* bi      = (const float*)d_in[4];
    const float* gcn_W   = (const float*)d_in[5];
    // d_in[6] gcn_b cancels under training-mode BN
    const float* gcn_gamma = (const float*)d_in[7];
    const float* gcn_beta  = (const float*)d_in[8];
    const float* Wg      = (const float*)d_in[9];
    // d_in[10] bg cancels under BN
    const float* att_src = (const float*)d_in[11];
    const float* att_dst = (const float*)d_in[12];
    const float* gat_gamma = (const float*)d_in[13];
    const float* gat_beta  = (const float*)d_in[14];
    const float* c1_W = (const float*)d_in[15];
    const float* c1_b = (const float*)d_in[16];
    const float* c2_W = (const float*)d_in[17];
    const float* c2_b = (const float*)d_in[18];
    const float* c3_W = (const float*)d_in[19];
    const float* c3_b = (const float*)d_in[20];
    float* out = (float*)d_out;

    const int NH = NN * HH;
    const int nh_blocks = (NH + 255) / 256;
    const int node_blocks = (NN + 63) / 64;   // 782

    // 1. input linear + relu  (x -> g_h)
    gemm64<FF, HH, true, 0, 0><<<dim3(node_blocks, 1), 256>>>(x, Wi, bi);

    // 2. CSR by dst (shared by GCN + GAT)
    zero_degi<<<(NN + 255) / 256, 256>>>();
    hist_dst<<<(EE + 255) / 256, 256>>>(ei);
    scan_offsets<<<1, 1024>>>();
    fill_csr<<<(EE + 255) / 256, 256>>>(ei);

    // 3. GCN layers
    for (int l = 0; l < LL; ++l) {
        gemm64<HH, HH, false, 1, 1><<<dim3(node_blocks, 1), 256>>>(nullptr, gcn_W + l * HH * HH, nullptr);
        gcn_gather<<<(NN + 3) / 4, 256>>>();
        zero_bn<<<1, HH>>>();
        bn_stats<<<128, dim3(HH, 8)>>>();
        bn_finalize<<<1, HH>>>(gcn_gamma + l * HH, nullptr);
        bn_apply_residual<false><<<nh_blocks, 256>>>(gcn_beta + l * HH);
    }

    // 4. GAT
    gemm64<HH, HEADS * HH, false, 1, 2><<<dim3(node_blocks, 4), 256>>>(nullptr, Wg, nullptr);
    gat_dots<<<(NN * HEADS * 32 + 255) / 256, 256>>>(att_src, att_dst);
    gat_ms<<<(NN * 32 + 255) / 256, 256>>>();
    gat_alpha<<<(EE * HEADS + 255) / 256, 256>>>();
    gat_gather<<<(NN + 3) / 4, 256>>>();
    zero_bn<<<1, HH>>>();
    bn_stats<<<128, dim3(HH, 8)>>>();
    bn_finalize<<<1, HH>>>(gat_gamma, nullptr);
    bn_apply_residual<true><<<nh_blocks, 256>>>(gat_beta);

    // 5. pooling + MLP
    pool_init<<<(GG * HH + 255) / 256, 256>>>();
    pool_reduce<<<(NN + 127) / 128, HH>>>(batch);
    mlp_kernel<<<GG, 128>>>(c1_W, c1_b, c2_W, c2_b, c3_W, c3_b, out);
}

// round 4
// speedup vs baseline: 3.0095x; 1.3339x over previous
#include <cuda_runtime.h>
#include <math.h>
#include <float.h>

#define NN 50000
#define EE 800000
#define FF 128
#define HH 64
#define HEADS 4
#define LL 3
#define GG 64
#define NCLS 2
#define EPS 1e-5f
#define CHUNKS 256
#define CHSZ ((NN + CHUNKS - 1) / CHUNKS)   // 196

// ---------------- scratch (device globals) ----------------------------------
__device__ __align__(16) float g_h[NN * HH];
__device__ __align__(16) float g_hw[NN * HH];
__device__ __align__(16) float g_acc[NN * HH];
__device__ __align__(16) float g_hg[NN * HEADS * HH];
__device__ float g_dinv[NN];
__device__ int   g_degi[NN];
__device__ int   g_off[NN];
__device__ int   g_cur[NN];
__device__ int   g_srcs[EE];
__device__ int   g_csum[CHUNKS];
__device__ int   g_cbase[CHUNKS];
__device__ float g_as[NN * HEADS];
__device__ float g_ad[NN * HEADS];
__device__ float g_aself[NN * HEADS];
__device__ __align__(16) float g_alpha[EE * HEADS];
__device__ double g_bnsum[HH];
__device__ double g_bnsq[HH];
__device__ __align__(16) float g_bnmu[HH];
__device__ __align__(16) float g_bnrstd[HH];
__device__ unsigned g_bncnt;
__device__ float g_psum[GG * HH];
__device__ float g_pmax[GG * HH];
__device__ float g_pcnt[GG];

// ---------------- helpers ----------------------------------------------------
__device__ __forceinline__ void atomicMaxF(float* addr, float v) {
    if (v >= 0.f) atomicMax((int*)addr, __float_as_int(v));
    else          atomicMin((unsigned int*)addr, __float_as_uint(v));
}
__device__ __forceinline__ float lrelu02(float x) { return x > 0.f ? x : 0.2f * x; }

// ---------------- tiled GEMM: Y[n,0..M) = X[n,0..K) @ W[K,M] -----------------
template <int K, int M, bool BIAS_RELU, int IN, int OUT>
__global__ void gemm64(const float* __restrict__ Xp, const float* __restrict__ W,
                       const float* __restrict__ bias) {
    const float* __restrict__ X = (IN == 0) ? Xp : (const float*)g_h;
    float* __restrict__ Y = (OUT == 0) ? g_h : (OUT == 1) ? g_hw : g_hg;
    __shared__ float xs[64][65];
    __shared__ float ws[64][65];
    const int tid = threadIdx.x;
    const int tx = tid & 15, ty = tid >> 4;
    const int nb = blockIdx.x * 64;
    const int mb = blockIdx.y * 64;
    float acc[4][4];
#pragma unroll
    for (int i = 0; i < 4; ++i)
#pragma unroll
        for (int j = 0; j < 4; ++j) acc[i][j] = 0.f;

    for (int kc = 0; kc < K; kc += 64) {
#pragma unroll
        for (int u = 0; u < 16; ++u) {
            int i = tid + u * 256;
            int node = i >> 6, k = i & 63;
            int gn = nb + node;
            xs[node][k] = (gn < NN) ? X[gn * K + kc + k] : 0.f;
        }
#pragma unroll
        for (int u = 0; u < 16; ++u) {
            int i = tid + u * 256;
            int k = i >> 6, m = i & 63;
            ws[k][m] = W[(kc + k) * M + mb + m];
        }
        __syncthreads();
#pragma unroll
        for (int k = 0; k < 64; ++k) {
            float xv[4], wv[4];
#pragma unroll
            for (int i = 0; i < 4; ++i) xv[i] = xs[ty + 16 * i][k];
#pragma unroll
            for (int j = 0; j < 4; ++j) wv[j] = ws[k][tx + 16 * j];
#pragma unroll
            for (int i = 0; i < 4; ++i)
#pragma unroll
                for (int j = 0; j < 4; ++j) acc[i][j] += xv[i] * wv[j];
        }
        __syncthreads();
    }
#pragma unroll
    for (int i = 0; i < 4; ++i) {
        int gn = nb + ty + 16 * i;
        if (gn >= NN) continue;
#pragma unroll
        for (int j = 0; j < 4; ++j) {
            int col = tx + 16 * j;
            float v = acc[i][j];
            if (BIAS_RELU) v = fmaxf(v + bias[mb + col], 0.f);
            Y[gn * M + mb + col] = v;
        }
    }
}

// ---------------- CSR build ---------------------------------------------------
__global__ void zero_degi() {
    int i = blockIdx.x * blockDim.x + threadIdx.x;
    if (i < NN) g_degi[i] = 0;
}
__global__ void hist_dst(const int* __restrict__ ei) {
    int e = blockIdx.x * blockDim.x + threadIdx.x;
    if (e < EE) atomicAdd(&g_degi[ei[EE + e]], 1);
}
__global__ void chunk_sums() {  // 32 blocks x 256: warp per chunk
    int w = (blockIdx.x * blockDim.x + threadIdx.x) >> 5;
    int lane = threadIdx.x & 31;
    if (w >= CHUNKS) return;
    int i0 = w * CHSZ, i1 = min(i0 + CHSZ, NN);
    int s = 0;
    for (int i = i0 + lane; i < i1; i += 32) s += g_degi[i];
#pragma unroll
    for (int o = 16; o; o >>= 1) s += __shfl_down_sync(0xffffffffu, s, o);
    if (lane == 0) g_csum[w] = s;
}
__global__ void chunk_scan() {  // 1 block x 256
    int t = threadIdx.x;
    int lane = t & 31, wid = t >> 5;
    int v = g_csum[t];
    int x = v;
#pragma unroll
    for (int o = 1; o < 32; o <<= 1) {
        int u = __shfl_up_sync(0xffffffffu, x, o);
        if (lane >= o) x += u;
    }
    __shared__ int ws[8];
    if (lane == 31) ws[wid] = x;
    __syncthreads();
    if (wid == 0 && lane < 8) {
        int w = ws[lane];
#pragma unroll
        for (int o = 1; o < 8; o <<= 1) {
            int u = __shfl_up_sync(0xffu, w, o);
            if (lane >= o) w += u;
        }
        ws[lane] = w;
    }
    __syncthreads();
    int incl = x + (wid ? ws[wid - 1] : 0);
    g_cbase[t] = incl - v;
}
__global__ void fill_offsets() {  // 32 blocks x 256: warp per chunk
    int w = (blockIdx.x * blockDim.x + threadIdx.x) >> 5;
    int lane = threadIdx.x & 31;
    if (w >= CHUNKS) return;
    int run = g_cbase[w];
    int i0 = w * CHSZ, i1 = min(i0 + CHSZ, NN);
    for (int base = i0; base < i1; base += 32) {
        int i = base + lane;
        int d = (i < i1) ? g_degi[i] : 0;
        int x = d;
#pragma unroll
        for (int o = 1; o < 32; o <<= 1) {
            int u = __shfl_up_sync(0xffffffffu, x, o);
            if (lane >= o) x += u;
        }
        if (i < i1) {
            int off = run + x - d;
            g_off[i] = off;
            g_cur[i] = off;
            g_dinv[i] = rsqrtf((float)d + 1.f);
        }
        run += __shfl_sync(0xffffffffu, x, 31);
    }
}
__global__ void fill_csr(const int* __restrict__ ei) {
    int e = blockIdx.x * blockDim.x + threadIdx.x;
    if (e >= EE) return;
    int src = ei[e], dst = ei[EE + e];
    int pos = atomicAdd(&g_cur[dst], 1);
    g_srcs[pos] = src;
}

// ---------------- GCN gather (float4, 16 thr/node) ---------------------------
__global__ void gcn_gather() {  // 256 thr = 16 nodes x 16 c4
    int t = threadIdx.x;
    int c4 = t & 15;
    int n = blockIdx.x * 16 + (t >> 4);
    if (n >= NN) return;
    const float4* hw4 = (const float4*)g_hw;
    float dn = g_dinv[n];
    int start = g_off[n], deg = g_degi[n];
    float4 a = hw4[n * 16 + c4];
    float w = dn * dn;
    float4 acc;
    acc.x = a.x * w; acc.y = a.y * w; acc.z = a.z * w; acc.w = a.w * w;
    int k = 0;
    for (; k + 4 <= deg; k += 4) {
        int s0 = g_srcs[start + k], s1 = g_srcs[start + k + 1];
        int s2 = g_srcs[start + k + 2], s3 = g_srcs[start + k + 3];
        float w0 = g_dinv[s0] * dn, w1 = g_dinv[s1] * dn;
        float w2 = g_dinv[s2] * dn, w3 = g_dinv[s3] * dn;
        float4 v0 = hw4[s0 * 16 + c4], v1 = hw4[s1 * 16 + c4];
        float4 v2 = hw4[s2 * 16 + c4], v3 = hw4[s3 * 16 + c4];
        acc.x += w0 * v0.x + w1 * v1.x + w2 * v2.x + w3 * v3.x;
        acc.y += w0 * v0.y + w1 * v1.y + w2 * v2.y + w3 * v3.y;
        acc.z += w0 * v0.z + w1 * v1.z + w2 * v2.z + w3 * v3.z;
        acc.w += w0 * v0.w + w1 * v1.w + w2 * v2.w + w3 * v3.w;
    }
    for (; k < deg; ++k) {
        int s0 = g_srcs[start + k];
        float w0 = g_dinv[s0] * dn;
        float4 v0 = hw4[s0 * 16 + c4];
        acc.x += w0 * v0.x; acc.y += w0 * v0.y; acc.z += w0 * v0.z; acc.w += w0 * v0.w;
    }
    ((float4*)g_acc)[n * 16 + c4] = acc;
}

// ---------------- BN: fused stats + finalize ----------------------------------
__global__ void bn_stats_fin(const float* __restrict__ gamma) {  // 128 blocks x (64,8)
    __shared__ double ss[8][HH];
    __shared__ double sq[8][HH];
    __shared__ bool is_last;
    int c = threadIdx.x, ty = threadIdx.y;
    double s = 0.0, q = 0.0;
    for (int r = blockIdx.x * 8 + ty; r < NN; r += gridDim.x * 8) {
        double v = (double)g_acc[r * HH + c];
        s += v; q += v * v;
    }
    ss[ty][c] = s; sq[ty][c] = q;
    __syncthreads();
    if (ty == 0) {
#pragma unroll
        for (int t = 1; t < 8; ++t) { s += ss[t][c]; q += sq[t][c]; }
        atomicAdd(&g_bnsum[c], s);
        atomicAdd(&g_bnsq[c], q);
    }
    __threadfence();
    __syncthreads();
    if (c == 0 && ty == 0) {
        unsigned old = atomicInc(&g_bncnt, gridDim.x - 1);
        is_last = (old == gridDim.x - 1);
    }
    __syncthreads();
    if (is_last && ty == 0) {
        __threadfence();
        double mu = g_bnsum[c] / (double)NN;
        double var = g_bnsq[c] / (double)NN - mu * mu;
        g_bnmu[c] = (float)mu;
        g_bnrstd[c] = rsqrtf((float)var + EPS) * gamma[c];
        g_bnsum[c] = 0.0;   // reset for next use (graph-replay safe)
        g_bnsq[c] = 0.0;
    }
}
template <bool ELU>
__global__ void bn_apply_residual(const float* __restrict__ beta) {
    int idx = blockIdx.x * blockDim.x + threadIdx.x;  // NN*16
    if (idx >= NN * 16) return;
    int c4 = idx & 15;
    float4 a = ((const float4*)g_acc)[idx];
    float4 mu = ((const float4*)g_bnmu)[c4];
    float4 rs = ((const float4*)g_bnrstd)[c4];
    float4 be = ((const float4*)beta)[c4];
    float4 h = ((const float4*)g_h)[idx];
    float v, o;
    float4 r;
    v = (a.x - mu.x) * rs.x + be.x; o = ELU ? (v > 0.f ? v : expf(v) - 1.f) : fmaxf(v, 0.f); r.x = o + h.x;
    v = (a.y - mu.y) * rs.y + be.y; o = ELU ? (v > 0.f ? v : expf(v) - 1.f) : fmaxf(v, 0.f); r.y = o + h.y;
    v = (a.z - mu.z) * rs.z + be.z; o = ELU ? (v > 0.f ? v : expf(v) - 1.f) : fmaxf(v, 0.f); r.z = o + h.z;
    v = (a.w - mu.w) * rs.w + be.w; o = ELU ? (v > 0.f ? v : expf(v) - 1.f) : fmaxf(v, 0.f); r.w = o + h.w;
    ((float4*)g_h)[idx] = r;
}

// ---------------- GAT ----------------------------------------------------------
__global__ void gat_dots(const float* __restrict__ att_s, const float* __restrict__ att_d) {
    int gt = blockIdx.x * blockDim.x + threadIdx.x;
    int gw = gt >> 5;
    int lane = gt & 31;
    if (gw >= NN * HEADS) return;
    int n = gw >> 2, hd = gw & 3;
    const float* row = g_hg + n * (HEADS * HH) + hd * HH;
    float v0 = row[lane], v1 = row[lane + 32];
    float s1 = v0 * att_s[hd * HH + lane] + v1 * att_s[hd * HH + lane + 32];
    float s2 = v0 * att_d[hd * HH + lane] + v1 * att_d[hd * HH + lane + 32];
#pragma unroll
    for (int o = 16; o; o >>= 1) {
        s1 += __shfl_down_sync(0xffffffffu, s1, o);
        s2 += __shfl_down_sync(0xffffffffu, s2, o);
    }
    if (lane == 0) { g_as[gw] = s1; g_ad[gw] = s2; }
}
// warp per node: online (m,s) per head, then alpha in the same kernel
__global__ void gat_msalpha() {
    int warp = (blockIdx.x * blockDim.x + threadIdx.x) >> 5;
    int lane = threadIdx.x & 31;
    if (warp >= NN) return;
    int n = warp;
    int hd = lane & 3, k0 = lane >> 2;
    float adv = g_ad[n * HEADS + hd];
    float asv = g_as[n * HEADS + hd];
    float lg_self = lrelu02(asv + adv);
    float m = -FLT_MAX, s = 0.f;
    if (k0 == 0) { m = lg_self; s = 1.f; }
    int start = g_off[n], deg = g_degi[n];
    for (int k = k0; k < deg; k += 8) {
        int sr = g_srcs[start + k];
        float lg = lrelu02(g_as[sr * HEADS + hd] + adv);
        if (lg > m) { s = s * expf(m - lg) + 1.f; m = lg; }
        else        { s += expf(lg - m); }
    }
#pragma unroll
    for (int o = 4; o < 32; o <<= 1) {
        float mo = __shfl_xor_sync(0xffffffffu, m, o);
        float so = __shfl_xor_sync(0xffffffffu, s, o);
        float M = fmaxf(m, mo);
        s = s * expf(m - M) + so * expf(mo - M);
        m = M;
    }
    float inv = 1.f / (s + 1e-16f);
    if (lane < 4) g_aself[n * HEADS + lane] = expf(lg_self - m) * inv;
    for (int k = k0; k < deg; k += 8) {
        int sr = g_srcs[start + k];
        float lg = lrelu02(g_as[sr * HEADS + hd] + adv);
        g_alpha[(start + k) * 4 + hd] = expf(lg - m) * inv;
    }
}
__global__ void gat_gather() {  // 256 thr = 16 nodes x 16 c4
    int t = threadIdx.x;
    int c4 = t & 15;
    int n = blockIdx.x * 16 + (t >> 4);
    if (n >= NN) return;
    const float4* hg4 = (const float4*)g_hg;
    int base = n * 64;
    float a0 = g_aself[n * 4 + 0], a1 = g_aself[n * 4 + 1];
    float a2 = g_aself[n * 4 + 2], a3 = g_aself[n * 4 + 3];
    float4 v0 = hg4[base + c4], v1 = hg4[base + 16 + c4];
    float4 v2 = hg4[base + 32 + c4], v3 = hg4[base + 48 + c4];
    float4 acc;
    acc.x = a0 * v0.x + a1 * v1.x + a2 * v2.x + a3 * v3.x;
    acc.y = a0 * v0.y + a1 * v1.y + a2 * v2.y + a3 * v3.y;
    acc.z = a0 * v0.z + a1 * v1.z + a2 * v2.z + a3 * v3.z;
    acc.w = a0 * v0.w + a1 * v1.w + a2 * v2.w + a3 * v3.w;
    int start = g_off[n], deg = g_degi[n];
    for (int k = 0; k < deg; ++k) {
        int pos = start + k;
        float4 al = ((const float4*)g_alpha)[pos];
        int sr = g_srcs[pos];
        int b = sr * 64;
        float4 u0 = hg4[b + c4], u1 = hg4[b + 16 + c4];
        float4 u2 = hg4[b + 32 + c4], u3 = hg4[b + 48 + c4];
        acc.x += al.x * u0.x + al.y * u1.x + al.z * u2.x + al.w * u3.x;
        acc.y += al.x * u0.y + al.y * u1.y + al.z * u2.y + al.w * u3.y;
        acc.z += al.x * u0.z + al.y * u1.z + al.z * u2.z + al.w * u3.z;
        acc.w += al.x * u0.w + al.y * u1.w + al.z * u2.w + al.w * u3.w;
    }
    acc.x *= 0.25f; acc.y *= 0.25f; acc.z *= 0.25f; acc.w *= 0.25f;
    ((float4*)g_acc)[n * 16 + c4] = acc;
}

// ---------------- pooling + MLP -------------------------------------------------
__global__ void pool_init() {
    int idx = blockIdx.x * blockDim.x + threadIdx.x;
    if (idx < GG * HH) { g_psum[idx] = 0.f; g_pmax[idx] = -FLT_MAX; }
    if (idx < GG) g_pcnt[idx] = 0.f;
}
__global__ void pool_reduce(const int* __restrict__ batch) {  // 64 thr, 128 nodes/block
    int c = threadIdx.x;
    int n0 = blockIdx.x * 128;
    int n1 = min(n0 + 128, NN);
    if (n0 >= NN) return;
    int cur = batch[n0];
    float sum = 0.f, mx = -FLT_MAX;
    int cnt = 0;
    for (int n = n0; n < n1; ++n) {
        int b = batch[n];
        if (b != cur) {
            atomicAdd(&g_psum[cur * HH + c], sum);
            atomicMaxF(&g_pmax[cur * HH + c], mx);
            if (c == 0) atomicAdd(&g_pcnt[cur], (float)cnt);
            sum = 0.f; mx = -FLT_MAX; cnt = 0; cur = b;
        }
        float v = g_h[n * HH + c];
        sum += v;
        mx = fmaxf(mx, v);
        cnt++;
    }
    atomicAdd(&g_psum[cur * HH + c], sum);
    atomicMaxF(&g_pmax[cur * HH + c], mx);
    if (c == 0) atomicAdd(&g_pcnt[cur], (float)cnt);
}
__global__ void mlp_kernel(const float* __restrict__ c1W, const float* __restrict__ c1b,
                           const float* __restrict__ c2W, const float* __restrict__ c2b,
                           const float* __restrict__ c3W, const float* __restrict__ c3b,
                           float* __restrict__ out) {
    __shared__ float z[2 * HH];
    __shared__ float z1[HH];
    __shared__ float z2[HH / 2];
    int g = blockIdx.x, t = threadIdx.x;
    if (t < HH) {
        float cnt = g_pcnt[g];
        float mean = g_psum[g * HH + t] / fmaxf(cnt, 1.f);
        float mx = g_pmax[g * HH + t];
        if (cnt < 0.5f) mx = 0.f;
        z[t] = mean;
        z[HH + t] = mx;
    }
    __syncthreads();
    if (t < HH) {
        float a = c1b[t];
#pragma unroll 4
        for (int k = 0; k < 2 * HH; ++k) a += z[k] * c1W[k * HH + t];
        z1[t] = fmaxf(a, 0.f);
    }
    __syncthreads();
    if (t < HH / 2) {
        float a = c2b[t];
#pragma unroll 4
        for (int k = 0; k < HH; ++k) a += z1[k] * c2W[k * (HH / 2) + t];
        z2[t] = fmaxf(a, 0.f);
    }
    __syncthreads();
    if (t < NCLS) {
        float a = c3b[t];
#pragma unroll
        for (int k = 0; k < HH / 2; ++k) a += z2[k] * c3W[k * NCLS + t];
        out[g * NCLS + t] = a;
    }
}

// ---------------- launch ----------------------------------------------------
extern "C" void kernel_launch(void* const* d_in, const int* in_sizes, int n_in,
                              void* d_out, int out_size) {
    const float* x       = (const float*)d_in[0];
    const int*   ei      = (const int*)d_in[1];
    const int*   batch   = (const int*)d_in[2];
    const float* Wi      = (const float*)d_in[3];
    const float* bi      = (const float*)d_in[4];
    const float* gcn_W   = (const float*)d_in[5];
    // d_in[6] gcn_b cancels under training-mode BN
    const float* gcn_gamma = (const float*)d_in[7];
    const float* gcn_beta  = (const float*)d_in[8];
    const float* Wg      = (const float*)d_in[9];
    // d_in[10] bg cancels under BN
    const float* att_src = (const float*)d_in[11];
    const float* att_dst = (const float*)d_in[12];
    const float* gat_gamma = (const float*)d_in[13];
    const float* gat_beta  = (const float*)d_in[14];
    const float* c1_W = (const float*)d_in[15];
    const float* c1_b = (const float*)d_in[16];
    const float* c2_W = (const float*)d_in[17];
    const float* c2_b = (const float*)d_in[18];
    const float* c3_W = (const float*)d_in[19];
    const float* c3_b = (const float*)d_in[20];
    float* out = (float*)d_out;

    const int node_blocks = (NN + 63) / 64;        // 782
    const int g16_blocks = (NN + 15) / 16;         // 3125
    const int apply_blocks = (NN * 16 + 255) / 256;

    // 1. input linear + relu
    gemm64<FF, HH, true, 0, 0><<<dim3(node_blocks, 1), 256>>>(x, Wi, bi);

    // 2. CSR by dst
    zero_degi<<<(NN + 255) / 256, 256>>>();
    hist_dst<<<(EE + 255) / 256, 256>>>(ei);
    chunk_sums<<<32, 256>>>();
    chunk_scan<<<1, 256>>>();
    fill_offsets<<<32, 256>>>();
    fill_csr<<<(EE + 255) / 256, 256>>>(ei);

    // 3. GCN layers
    for (int l = 0; l < LL; ++l) {
        gemm64<HH, HH, false, 1, 1><<<dim3(node_blocks, 1), 256>>>(nullptr, gcn_W + l * HH * HH, nullptr);
        gcn_gather<<<g16_blocks, 256>>>();
        bn_stats_fin<<<128, dim3(HH, 8)>>>(gcn_gamma + l * HH);
        bn_apply_residual<false><<<apply_blocks, 256>>>(gcn_beta + l * HH);
    }

    // 4. GAT
    gemm64<HH, HEADS * HH, false, 1, 2><<<dim3(node_blocks, 4), 256>>>(nullptr, Wg, nullptr);
    gat_dots<<<(NN * HEADS * 32 + 255) / 256, 256>>>(att_src, att_dst);
    gat_msalpha<<<(NN * 32 + 255) / 256, 256>>>();
    gat_gather<<<g16_blocks, 256>>>();
    bn_stats_fin<<<128, dim3(HH, 8)>>>(gat_gamma);
    bn_apply_residual<true><<<apply_blocks, 256>>>(gat_beta);

    // 5. pooling + MLP
    pool_init<<<(GG * HH + 255) / 256, 256>>>();
    pool_reduce<<<(NN + 127) / 128, HH>>>(batch);
    mlp_kernel<<<GG, 128>>>(c1_W, c1_b, c2_W, c2_b, c3_W, c3_b, out);
}

// round 6
// speedup vs baseline: 3.1615x; 1.0505x over previous
#include <cuda_runtime.h>
#include <math.h>
#include <float.h>

#define NN 50000
#define EE 800000
#define FF 128
#define HH 64
#define HEADS 4
#define LL 3
#define GG 64
#define NCLS 2
#define EPS 1e-5f
#define CHUNKS 256
#define CHSZ ((NN + CHUNKS - 1) / CHUNKS)

// ---------------- scratch (device globals) ----------------------------------
__device__ __align__(16) float g_h[NN * HH];
__device__ __align__(16) float g_hw[NN * HH];
__device__ __align__(16) float g_acc[NN * HH];
__device__ __align__(16) float g_hg[NN * HEADS * HH];
__device__ float g_dinv[NN];
__device__ int   g_degi[NN];
__device__ int   g_off[NN];
__device__ int   g_cur[NN];
__device__ int   g_srcs[EE];
__device__ int   g_csum[CHUNKS];
__device__ int   g_cbase[CHUNKS];
__device__ float g_as[NN * HEADS];
__device__ float g_ad[NN * HEADS];
__device__ float g_aself[NN * HEADS];
__device__ __align__(16) float g_alpha[EE * HEADS];
__device__ double g_bnsum[HH];
__device__ double g_bnsq[HH];
__device__ __align__(16) float g_bnmu[HH];
__device__ __align__(16) float g_bnrstd[HH];
__device__ unsigned g_bncnt;
__device__ float g_psum[GG * HH];
__device__ float g_pmax[GG * HH];
__device__ float g_pcnt[GG];

// ---------------- helpers ----------------------------------------------------
__device__ __forceinline__ void atomicMaxF(float* addr, float v) {
    if (v >= 0.f) atomicMax((int*)addr, __float_as_int(v));
    else          atomicMin((unsigned int*)addr, __float_as_uint(v));
}
__device__ __forceinline__ float lrelu02(float x) { return x > 0.f ? x : 0.2f * x; }

// ---------------- tiled GEMM with optional fused BN-in and fused dots --------
// INMODE: 0 = param X, 1 = g_h, 2 = fused BN: X := relu((g_acc-mu)*rstd+beta)+g_h
// HOUT (INMODE==2 only): 0 -> h_new written to g_h (requires gridDim.y==1),
//                        1 -> h_new written to g_hw (race-free for gridDim.y>1)
// OUT: 0 -> g_h, 1 -> g_hw, 2 -> g_hg
template <int K, int M, int INMODE, int HOUT, int OUT, bool BIAS_RELU, bool DOTS>
__global__ void gemm64(const float* __restrict__ Xp, const float* __restrict__ W,
                       const float* __restrict__ bias, const float* __restrict__ beta,
                       const float* __restrict__ att_s, const float* __restrict__ att_d) {
    float* __restrict__ Y = (OUT == 0) ? g_h : (OUT == 1) ? g_hw : g_hg;
    __shared__ float xs[64][68];
    __shared__ float ws[64][68];
    const int tid = threadIdx.x;
    const int tx = tid & 15, ty = tid >> 4;
    const int nb = blockIdx.x * 64;
    const int mb = blockIdx.y * 64;
    float acc[4][4];
#pragma unroll
    for (int i = 0; i < 4; ++i)
#pragma unroll
        for (int j = 0; j < 4; ++j) acc[i][j] = 0.f;

    for (int kc = 0; kc < K; kc += 64) {
#pragma unroll
        for (int u = 0; u < 4; ++u) {
            int i = tid + u * 256;                 // float4 index 0..1023
            int node = i >> 4, k4 = i & 15;
            int gn = nb + node;
            float4 r = make_float4(0.f, 0.f, 0.f, 0.f);
            if (gn < NN) {
                if (INMODE == 2) {
                    float4 a = ((const float4*)g_acc)[gn * 16 + k4];
                    float4 h = ((const float4*)g_h)[gn * 16 + k4];
                    float4 mu = ((const float4*)g_bnmu)[k4];
                    float4 rs = ((const float4*)g_bnrstd)[k4];
                    float4 be = ((const float4*)beta)[k4];
                    r.x = fmaxf((a.x - mu.x) * rs.x + be.x, 0.f) + h.x;
                    r.y = fmaxf((a.y - mu.y) * rs.y + be.y, 0.f) + h.y;
                    r.z = fmaxf((a.z - mu.z) * rs.z + be.z, 0.f) + h.z;
                    r.w = fmaxf((a.w - mu.w) * rs.w + be.w, 0.f) + h.w;
                    if (blockIdx.y == 0) {
                        float4* Hdst = (HOUT == 0) ? (float4*)g_h : (float4*)g_hw;
                        Hdst[gn * 16 + k4] = r;
                    }
                } else {
                    const float4* X4 = (INMODE == 0) ? (const float4*)Xp : (const float4*)g_h;
                    r = X4[gn * (K / 4) + (kc >> 2) + k4];
                }
            }
            *(float4*)&xs[node][k4 * 4] = r;
        }
#pragma unroll
        for (int u = 0; u < 4; ++u) {
            int i = tid + u * 256;
            int k = i >> 4, m4 = i & 15;
            float4 w = *(const float4*)&W[(kc + k) * M + mb + m4 * 4];
            *(float4*)&ws[k][m4 * 4] = w;
        }
        __syncthreads();
#pragma unroll
        for (int k = 0; k < 64; ++k) {
            float xv[4], wv[4];
#pragma unroll
            for (int i = 0; i < 4; ++i) xv[i] = xs[ty + 16 * i][k];
#pragma unroll
            for (int j = 0; j < 4; ++j) wv[j] = ws[k][tx + 16 * j];
#pragma unroll
            for (int i = 0; i < 4; ++i)
#pragma unroll
                for (int j = 0; j < 4; ++j) acc[i][j] += xv[i] * wv[j];
        }
        __syncthreads();
    }
#pragma unroll
    for (int i = 0; i < 4; ++i) {
        int gn = nb + ty + 16 * i;
        if (gn >= NN) continue;
#pragma unroll
        for (int j = 0; j < 4; ++j) {
            int col = tx + 16 * j;
            float v = acc[i][j];
            if (BIAS_RELU) v = fmaxf(v + bias[mb + col], 0.f);
            Y[gn * M + mb + col] = v;
        }
    }
    if (DOTS) {
        const int head = blockIdx.y;
#pragma unroll
        for (int i = 0; i < 4; ++i) {
            int gn = nb + ty + 16 * i;
            float ps = 0.f, pd = 0.f;
#pragma unroll
            for (int j = 0; j < 4; ++j) {
                int c = tx + 16 * j;
                ps += acc[i][j] * att_s[head * HH + c];
                pd += acc[i][j] * att_d[head * HH + c];
            }
#pragma unroll
            for (int o = 8; o; o >>= 1) {
                ps += __shfl_down_sync(0xffffffffu, ps, o, 16);
                pd += __shfl_down_sync(0xffffffffu, pd, o, 16);
            }
            if (tx == 0 && gn < NN) {
                atomicAdd(&g_as[gn * HEADS + head], ps);
                atomicAdd(&g_ad[gn * HEADS + head], pd);
            }
        }
    }
}

// ---------------- CSR build + misc init ---------------------------------------
__global__ void init_misc() {
    int i = blockIdx.x * blockDim.x + threadIdx.x;
    if (i < NN) g_degi[i] = 0;
    if (i < NN * HEADS) { g_as[i] = 0.f; g_ad[i] = 0.f; }
}
__global__ void hist_dst(const int* __restrict__ ei) {
    int e = blockIdx.x * blockDim.x + threadIdx.x;
    if (e < EE) atomicAdd(&g_degi[ei[EE + e]], 1);
}
__global__ void chunk_sums() {
    int w = (blockIdx.x * blockDim.x + threadIdx.x) >> 5;
    int lane = threadIdx.x & 31;
    if (w >= CHUNKS) return;
    int i0 = w * CHSZ, i1 = min(i0 + CHSZ, NN);
    int s = 0;
    for (int i = i0 + lane; i < i1; i += 32) s += g_degi[i];
#pragma unroll
    for (int o = 16; o; o >>= 1) s += __shfl_down_sync(0xffffffffu, s, o);
    if (lane == 0) g_csum[w] = s;
}
__global__ void chunk_scan() {
    int t = threadIdx.x;
    int lane = t & 31, wid = t >> 5;
    int v = g_csum[t];
    int x = v;
#pragma unroll
    for (int o = 1; o < 32; o <<= 1) {
        int u = __shfl_up_sync(0xffffffffu, x, o);
        if (lane >= o) x += u;
    }
    __shared__ int ws[8];
    if (lane == 31) ws[wid] = x;
    __syncthreads();
    if (wid == 0 && lane < 8) {
        int w = ws[lane];
#pragma unroll
        for (int o = 1; o < 8; o <<= 1) {
            int u = __shfl_up_sync(0xffu, w, o);
            if (lane >= o) w += u;
        }
        ws[lane] = w;
    }
    __syncthreads();
    g_cbase[t] = x + (wid ? ws[wid - 1] : 0) - v;
}
__global__ void fill_offsets() {
    int w = (blockIdx.x * blockDim.x + threadIdx.x) >> 5;
    int lane = threadIdx.x & 31;
    if (w >= CHUNKS) return;
    int run = g_cbase[w];
    int i0 = w * CHSZ, i1 = min(i0 + CHSZ, NN);
    for (int base = i0; base < i1; base += 32) {
        int i = base + lane;
        int d = (i < i1) ? g_degi[i] : 0;
        int x = d;
#pragma unroll
        for (int o = 1; o < 32; o <<= 1) {
            int u = __shfl_up_sync(0xffffffffu, x, o);
            if (lane >= o) x += u;
        }
        if (i < i1) {
            int off = run + x - d;
            g_off[i] = off;
            g_cur[i] = off;
            g_dinv[i] = rsqrtf((float)d + 1.f);
        }
        run += __shfl_sync(0xffffffffu, x, 31);
    }
}
__global__ void fill_csr(const int* __restrict__ ei) {
    int e = blockIdx.x * blockDim.x + threadIdx.x;
    if (e >= EE) return;
    int src = ei[e], dst = ei[EE + e];
    int pos = atomicAdd(&g_cur[dst], 1);
    g_srcs[pos] = src;
}

// ---------------- GCN gather ---------------------------------------------------
__global__ void gcn_gather() {
    int t = threadIdx.x;
    int c4 = t & 15;
    int n = blockIdx.x * 16 + (t >> 4);
    if (n >= NN) return;
    const float4* hw4 = (const float4*)g_hw;
    float dn = g_dinv[n];
    int start = g_off[n], deg = g_degi[n];
    float4 a = hw4[n * 16 + c4];
    float w = dn * dn;
    float4 acc;
    acc.x = a.x * w; acc.y = a.y * w; acc.z = a.z * w; acc.w = a.w * w;
    int k = 0;
    for (; k + 4 <= deg; k += 4) {
        int s0 = g_srcs[start + k], s1 = g_srcs[start + k + 1];
        int s2 = g_srcs[start + k + 2], s3 = g_srcs[start + k + 3];
        float w0 = g_dinv[s0] * dn, w1 = g_dinv[s1] * dn;
        float w2 = g_dinv[s2] * dn, w3 = g_dinv[s3] * dn;
        float4 v0 = hw4[s0 * 16 + c4], v1 = hw4[s1 * 16 + c4];
        float4 v2 = hw4[s2 * 16 + c4], v3 = hw4[s3 * 16 + c4];
        acc.x += w0 * v0.x + w1 * v1.x + w2 * v2.x + w3 * v3.x;
        acc.y += w0 * v0.y + w1 * v1.y + w2 * v2.y + w3 * v3.y;
        acc.z += w0 * v0.z + w1 * v1.z + w2 * v2.z + w3 * v3.z;
        acc.w += w0 * v0.w + w1 * v1.w + w2 * v2.w + w3 * v3.w;
    }
    for (; k < deg; ++k) {
        int s0 = g_srcs[start + k];
        float w0 = g_dinv[s0] * dn;
        float4 v0 = hw4[s0 * 16 + c4];
        acc.x += w0 * v0.x; acc.y += w0 * v0.y; acc.z += w0 * v0.z; acc.w += w0 * v0.w;
    }
    ((float4*)g_acc)[n * 16 + c4] = acc;
}

// ---------------- BN: fused stats + finalize ------------------------------------
__global__ void bn_stats_fin(const float* __restrict__ gamma) {
    __shared__ double ss[8][HH];
    __shared__ double sq[8][HH];
    __shared__ bool is_last;
    int c = threadIdx.x, ty = threadIdx.y;
    double s = 0.0, q = 0.0;
    for (int r = blockIdx.x * 8 + ty; r < NN; r += gridDim.x * 8) {
        double v = (double)g_acc[r * HH + c];
        s += v; q += v * v;
    }
    ss[ty][c] = s; sq[ty][c] = q;
    __syncthreads();
    if (ty == 0) {
#pragma unroll
        for (int t = 1; t < 8; ++t) { s += ss[t][c]; q += sq[t][c]; }
        atomicAdd(&g_bnsum[c], s);
        atomicAdd(&g_bnsq[c], q);
    }
    __threadfence();
    __syncthreads();
    if (c == 0 && ty == 0) {
        unsigned old = atomicInc(&g_bncnt, gridDim.x - 1);
        is_last = (old == gridDim.x - 1);
    }
    __syncthreads();
    if (is_last && ty == 0) {
        __threadfence();
        double mu = g_bnsum[c] / (double)NN;
        double var = g_bnsq[c] / (double)NN - mu * mu;
        g_bnmu[c] = (float)mu;
        g_bnrstd[c] = rsqrtf((float)var + EPS) * gamma[c];
        g_bnsum[c] = 0.0;
        g_bnsq[c] = 0.0;
    }
}

// ---------------- GAT -------------------------------------------------------------
__global__ void gat_msalpha() {
    int warp = (blockIdx.x * blockDim.x + threadIdx.x) >> 5;
    int lane = threadIdx.x & 31;
    if (warp >= NN) return;
    int n = warp;
    int hd = lane & 3, k0 = lane >> 2;
    float adv = g_ad[n * HEADS + hd];
    float asv = g_as[n * HEADS + hd];
    float lg_self = lrelu02(asv + adv);
    float m = -FLT_MAX, s = 0.f;
    if (k0 == 0) { m = lg_self; s = 1.f; }
    int start = g_off[n], deg = g_degi[n];
    for (int k = k0; k < deg; k += 8) {
        int sr = g_srcs[start + k];
        float lg = lrelu02(g_as[sr * HEADS + hd] + adv);
        if (lg > m) { s = s * expf(m - lg) + 1.f; m = lg; }
        else        { s += expf(lg - m); }
    }
#pragma unroll
    for (int o = 4; o < 32; o <<= 1) {
        float mo = __shfl_xor_sync(0xffffffffu, m, o);
        float so = __shfl_xor_sync(0xffffffffu, s, o);
        float M = fmaxf(m, mo);
        s = s * expf(m - M) + so * expf(mo - M);
        m = M;
    }
    float inv = 1.f / (s + 1e-16f);
    if (lane < 4) g_aself[n * HEADS + lane] = expf(lg_self - m) * inv;
    for (int k = k0; k < deg; k += 8) {
        int sr = g_srcs[start + k];
        float lg = lrelu02(g_as[sr * HEADS + hd] + adv);
        g_alpha[(start + k) * 4 + hd] = expf(lg - m) * inv;
    }
}
__global__ void gat_gather() {
    int t = threadIdx.x;
    int c4 = t & 15;
    int n = blockIdx.x * 16 + (t >> 4);
    if (n >= NN) return;
    const float4* hg4 = (const float4*)g_hg;
    int base = n * 64;
    float a0 = g_aself[n * 4 + 0], a1 = g_aself[n * 4 + 1];
    float a2 = g_aself[n * 4 + 2], a3 = g_aself[n * 4 + 3];
    float4 v0 = hg4[base + c4], v1 = hg4[base + 16 + c4];
    float4 v2 = hg4[base + 32 + c4], v3 = hg4[base + 48 + c4];
    float4 acc;
    acc.x = a0 * v0.x + a1 * v1.x + a2 * v2.x + a3 * v3.x;
    acc.y = a0 * v0.y + a1 * v1.y + a2 * v2.y + a3 * v3.y;
    acc.z = a0 * v0.z + a1 * v1.z + a2 * v2.z + a3 * v3.z;
    acc.w = a0 * v0.w + a1 * v1.w + a2 * v2.w + a3 * v3.w;
    int start = g_off[n], deg = g_degi[n];
    for (int k = 0; k < deg; ++k) {
        int pos = start + k;
        float4 al = ((const float4*)g_alpha)[pos];
        int sr = g_srcs[pos];
        int b = sr * 64;
        float4 u0 = hg4[b + c4], u1 = hg4[b + 16 + c4];
        float4 u2 = hg4[b + 32 + c4], u3 = hg4[b + 48 + c4];
        acc.x += al.x * u0.x + al.y * u1.x + al.z * u2.x + al.w * u3.x;
        acc.y += al.x * u0.y + al.y * u1.y + al.z * u2.y + al.w * u3.y;
        acc.z += al.x * u0.z + al.y * u1.z + al.z * u2.z + al.w * u3.z;
        acc.w += al.x * u0.w + al.y * u1.w + al.z * u2.w + al.w * u3.w;
    }
    acc.x *= 0.25f; acc.y *= 0.25f; acc.z *= 0.25f; acc.w *= 0.25f;
    ((float4*)g_acc)[n * 16 + c4] = acc;
}

// ---------------- pooling (fused GAT BN+ELU+residual) + MLP ----------------------
__global__ void pool_init() {
    int idx = blockIdx.x * blockDim.x + threadIdx.x;
    if (idx < GG * HH) { g_psum[idx] = 0.f; g_pmax[idx] = -FLT_MAX; }
    if (idx < GG) g_pcnt[idx] = 0.f;
}
// residual read from g_hw (h_new written by the GAT gemm's y==0 block)
__global__ void pool_fused(const int* __restrict__ batch, const float* __restrict__ beta) {
    int c = threadIdx.x;
    int n0 = blockIdx.x * 128;
    int n1 = min(n0 + 128, NN);
    if (n0 >= NN) return;
    float mu = g_bnmu[c], rs = g_bnrstd[c], be = beta[c];
    int cur = batch[n0];
    float sum = 0.f, mx = -FLT_MAX;
    int cnt = 0;
    for (int n = n0; n < n1; ++n) {
        int b = batch[n];
        if (b != cur) {
            atomicAdd(&g_psum[cur * HH + c], sum);
            atomicMaxF(&g_pmax[cur * HH + c], mx);
            if (c == 0) atomicAdd(&g_pcnt[cur], (float)cnt);
            sum = 0.f; mx = -FLT_MAX; cnt = 0; cur = b;
        }
        float a = g_acc[n * HH + c];
        float v = (a - mu) * rs + be;
        v = (v > 0.f ? v : expf(v) - 1.f) + g_hw[n * HH + c];
        sum += v;
        mx = fmaxf(mx, v);
        cnt++;
    }
    atomicAdd(&g_psum[cur * HH + c], sum);
    atomicMaxF(&g_pmax[cur * HH + c], mx);
    if (c == 0) atomicAdd(&g_pcnt[cur], (float)cnt);
}
__global__ void mlp_kernel(const float* __restrict__ c1W, const float* __restrict__ c1b,
                           const float* __restrict__ c2W, const float* __restrict__ c2b,
                           const float* __restrict__ c3W, const float* __restrict__ c3b,
                           float* __restrict__ out) {
    __shared__ float z[2 * HH];
    __shared__ float z1[HH];
    __shared__ float z2[HH / 2];
    int g = blockIdx.x, t = threadIdx.x;
    if (t < HH) {
        float cnt = g_pcnt[g];
        float mean = g_psum[g * HH + t] / fmaxf(cnt, 1.f);
        float mx = g_pmax[g * HH + t];
        if (cnt < 0.5f) mx = 0.f;
        z[t] = mean;
        z[HH + t] = mx;
    }
    __syncthreads();
    if (t < HH) {
        float a = c1b[t];
#pragma unroll 4
        for (int k = 0; k < 2 * HH; ++k) a += z[k] * c1W[k * HH + t];
        z1[t] = fmaxf(a, 0.f);
    }
    __syncthreads();
    if (t < HH / 2) {
        float a = c2b[t];
#pragma unroll 4
        for (int k = 0; k < HH; ++k) a += z1[k] * c2W[k * (HH / 2) + t];
        z2[t] = fmaxf(a, 0.f);
    }
    __syncthreads();
    if (t < NCLS) {
        float a = c3b[t];
#pragma unroll
        for (int k = 0; k < HH / 2; ++k) a += z2[k] * c3W[k * NCLS + t];
        out[g * NCLS + t] = a;
    }
}

// ---------------- launch ----------------------------------------------------
extern "C" void kernel_launch(void* const* d_in, const int* in_sizes, int n_in,
                              void* d_out, int out_size) {
    const float* x       = (const float*)d_in[0];
    const int*   ei      = (const int*)d_in[1];
    const int*   batch   = (const int*)d_in[2];
    const float* Wi      = (const float*)d_in[3];
    const float* bi      = (const float*)d_in[4];
    const float* gcn_W   = (const float*)d_in[5];
    // d_in[6] gcn_b cancels under training-mode BN
    const float* gcn_gamma = (const float*)d_in[7];
    const float* gcn_beta  = (const float*)d_in[8];
    const float* Wg      = (const float*)d_in[9];
    // d_in[10] bg cancels under BN
    const float* att_src = (const float*)d_in[11];
    const float* att_dst = (const float*)d_in[12];
    const float* gat_gamma = (const float*)d_in[13];
    const float* gat_beta  = (const float*)d_in[14];
    const float* c1_W = (const float*)d_in[15];
    const float* c1_b = (const float*)d_in[16];
    const float* c2_W = (const float*)d_in[17];
    const float* c2_b = (const float*)d_in[18];
    const float* c3_W = (const float*)d_in[19];
    const float* c3_b = (const float*)d_in[20];
    float* out = (float*)d_out;

    const int node_blocks = (NN + 63) / 64;
    const int g16_blocks = (NN + 15) / 16;

    // 1. input linear + relu (x -> g_h)
    gemm64<FF, HH, 0, 0, 0, true, false><<<dim3(node_blocks, 1), 256>>>(
        x, Wi, bi, nullptr, nullptr, nullptr);

    // 2. CSR + zero attention accumulators
    init_misc<<<(NN * HEADS + 255) / 256, 256>>>();
    hist_dst<<<(EE + 255) / 256, 256>>>(ei);
    chunk_sums<<<32, 256>>>();
    chunk_scan<<<1, 256>>>();
    fill_offsets<<<32, 256>>>();
    fill_csr<<<(EE + 255) / 256, 256>>>(ei);

    // 3. GCN layer 0 (plain read of g_h)
    gemm64<HH, HH, 1, 0, 1, false, false><<<dim3(node_blocks, 1), 256>>>(
        nullptr, gcn_W, nullptr, nullptr, nullptr, nullptr);
    gcn_gather<<<g16_blocks, 256>>>();
    bn_stats_fin<<<128, dim3(HH, 8)>>>(gcn_gamma);
    // GCN layers 1,2: fused BN(prev)+ReLU+residual in X-staging; h_new -> g_h (grid.y==1, safe)
    for (int l = 1; l < LL; ++l) {
        gemm64<HH, HH, 2, 0, 1, false, false><<<dim3(node_blocks, 1), 256>>>(
            nullptr, gcn_W + l * HH * HH, nullptr, gcn_beta + (l - 1) * HH, nullptr, nullptr);
        gcn_gather<<<g16_blocks, 256>>>();
        bn_stats_fin<<<128, dim3(HH, 8)>>>(gcn_gamma + l * HH);
    }

    // 4. GAT: gemm applies layer-2 BN; h_new -> g_hw (HOUT=1, race-free across grid.y=4);
    //    writes g_hg; fused attention dots
    gemm64<HH, HEADS * HH, 2, 1, 2, false, true><<<dim3(node_blocks, 4), 256>>>(
        nullptr, Wg, nullptr, gcn_beta + 2 * HH, att_src, att_dst);
    gat_msalpha<<<(NN * 32 + 255) / 256, 256>>>();
    gat_gather<<<g16_blocks, 256>>>();
    bn_stats_fin<<<128, dim3(HH, 8)>>>(gat_gamma);

    // 5. pooling (fused GAT BN+ELU+residual, residual from g_hw) + MLP
    pool_init<<<(GG * HH + 255) / 256, 256>>>();
    pool_fused<<<(NN + 127) / 128, HH>>>(batch, gat_beta);
    mlp_kernel<<<GG, 128>>>(c1_W, c1_b, c2_W, c2_b, c3_W, c3_b, out);
}